// round 10
// baseline (speedup 1.0000x reference)
#include <cuda_runtime.h>
#include <math.h>
#include <stdint.h>

#define IMG    64
#define NSLICE 16
#define NCOIL  4
#define NSING  4
#define NECHO  3
#define NRO    32
#define NPT    96
#define NEC    (NECHO * NCOIL)   // 12
#define NPIX   (IMG * IMG)       // 4096

// scf[kz][c][ne=n*3+e][pix]  (25 MB)   pixel index = X*64+Y (X major)
__device__ float2 g_scf[NSLICE * NCOIL * (NSING * NECHO) * NPIX];
// transposed singulars: tsing[ne][z][pix]  (6.3 MB)
__device__ float2 g_tsing[(NSING * NECHO) * NSLICE * NPIX];
// phase tables [r][x|y][p]
__device__ float2 g_exp_[NRO * IMG * NPT];   // exp(-i*w0*(x-32)) = (re, im)
__device__ float2 g_ey_[NRO * IMG * NPT];    // exp(-i*w1*(y-32))

// ---------------------------------------------------------------------------
// helpers
// ---------------------------------------------------------------------------
__device__ __forceinline__ float tf32r(float f) {
    uint32_t u;
    asm("cvt.rn.tf32.f32 %0, %1;" : "=r"(u) : "f"(f));
    return __uint_as_float(u);
}
__device__ __forceinline__ void mma_tf32(float* d, const uint32_t* a, const uint32_t* b) {
    asm volatile(
        "mma.sync.aligned.m16n8k8.row.col.f32.tf32.tf32.f32 "
        "{%0,%1,%2,%3}, {%4,%5,%6,%7}, {%8,%9}, {%0,%1,%2,%3};"
        : "+f"(d[0]), "+f"(d[1]), "+f"(d[2]), "+f"(d[3])
        : "r"(a[0]), "r"(a[1]), "r"(a[2]), "r"(a[3]), "r"(b[0]), "r"(b[1]));
}

// ---------------------------------------------------------------------------
// Transpose: singulars [pix][z][ne]{2} -> g_tsing [ne][z][pix]{2}
// grid (16 pixblk, 16 z), block 256.  Dense coalesced reads and writes.
// ---------------------------------------------------------------------------
__global__ __launch_bounds__(256)
void transpose_kernel(const float* __restrict__ singulars)   // [64,64,16,4,3,2]
{
    __shared__ float sS[256][25];   // 24 floats + pad
    const int z  = blockIdx.y;
    const int pb = blockIdx.x * 256;
    const int t  = threadIdx.x;

    const float4* src = (const float4*)(singulars + (size_t)(pb + t) * 384 + z * 24);
#pragma unroll
    for (int q = 0; q < 6; ++q) {
        float4 f = src[q];
        sS[t][4 * q + 0] = f.x; sS[t][4 * q + 1] = f.y;
        sS[t][4 * q + 2] = f.z; sS[t][4 * q + 3] = f.w;
    }
    __syncthreads();

#pragma unroll
    for (int j = 0; j < 12; ++j) {
        g_tsing[((size_t)j * NSLICE + z) * NPIX + pb + t]
            = make_float2(sS[t][2 * j], sS[t][2 * j + 1]);
    }
}

// ---------------------------------------------------------------------------
// Stage A (e-split): z-DFT of sign(z)*tsing*smap for one (c, ne) per block-row.
// grid (16 pixblk, 48 = c + 4*ne), block 256.  acc[16 kz] complex.
// All global accesses coalesced / single-line-per-thread.
// ---------------------------------------------------------------------------
__global__ __launch_bounds__(256, 4)
void stageA_kernel(const float* __restrict__ smap)   // [4,64,64,16,2]
{
    const int pix = blockIdx.x * 256 + threadIdx.x;
    const int j   = blockIdx.y;
    const int c   = j & 3;
    const int ne  = j >> 2;            // n*3+e

    // W[z][kz] = sign(z) * exp(-2pi*i*kz*z/16)
    __shared__ float2 W[NSLICE][NSLICE];
    {
        int z = threadIdx.x >> 4, kz = threadIdx.x & 15;
        float ang = -(2.0f * (float)M_PI / (float)NSLICE) * (float)(kz * z);
        float s, co; sincosf(ang, &s, &co);
        float sgn = (z & 1) ? -1.0f : 1.0f;
        W[z][kz] = make_float2(co * sgn, s * sgn);
    }
    __syncthreads();

    const float2* vsrc = g_tsing + (size_t)ne * NSLICE * NPIX + pix;
    const float2* ssrc = (const float2*)(smap) + ((size_t)c * NPIX + pix) * NSLICE;

    float accr[NSLICE], acci[NSLICE];
#pragma unroll
    for (int kz = 0; kz < NSLICE; ++kz) { accr[kz] = 0.f; acci[kz] = 0.f; }

#pragma unroll
    for (int z = 0; z < NSLICE; ++z) {
        float2 v  = vsrc[(size_t)z * NPIX];
        float2 sm = ssrc[z];
        float tr = v.x * sm.x - v.y * sm.y;
        float ti = v.x * sm.y + v.y * sm.x;
#pragma unroll
        for (int kz = 0; kz < NSLICE; ++kz) {
            float2 w = W[z][kz];
            accr[kz] = fmaf(tr, w.x, accr[kz]);
            accr[kz] = fmaf(-ti, w.y, accr[kz]);
            acci[kz] = fmaf(tr, w.y, acci[kz]);
            acci[kz] = fmaf(ti, w.x, acci[kz]);
        }
    }

#pragma unroll
    for (int kz = 0; kz < NSLICE; ++kz) {
        g_scf[(((size_t)kz * NCOIL + c) * 12 + ne) * NPIX + pix]
            = make_float2(accr[kz], acci[kz]);
    }
}

// ---------------------------------------------------------------------------
// Phase tables, parallel over 4 segments of 16. grid 32, block 384.
// ---------------------------------------------------------------------------
__global__ __launch_bounds__(384)
void exgen_kernel(const float* __restrict__ ktraj)   // [1,32,96,2]
{
    const int r = blockIdx.x;
    const int p = threadIdx.x % NPT;
    const int g = threadIdx.x / NPT;       // 0..3, 16 steps each
    const float w0 = ktraj[(r * NPT + p) * 2 + 0];
    const float w1 = ktraj[(r * NPT + p) * 2 + 1];

    {
        float s, c; sincosf(w0, &s, &c);                      // step exp(-i*w0)
        float pr, pi; sincosf(w0 * (32.0f - g * 16.0f), &pi, &pr);
#pragma unroll 4
        for (int jj = 0; jj < 16; ++jj) {
            int x = g * 16 + jj;
            g_exp_[((size_t)r * IMG + x) * NPT + p] = make_float2(pr, pi);
            float t = pr;
            pr = fmaf(pr, c, pi * s);
            pi = fmaf(pi, c, -(t * s));
        }
    }
    {
        float s, c; sincosf(w1, &s, &c);
        float pr, pi; sincosf(w1 * (32.0f - g * 16.0f), &pi, &pr);
#pragma unroll 4
        for (int jj = 0; jj < 16; ++jj) {
            int y = g * 16 + jj;
            g_ey_[((size_t)r * IMG + y) * NPT + p] = make_float2(pr, pi);
            float t = pr;
            pr = fmaf(pr, c, pi * s);
            pi = fmaf(pi, c, -(t * s));
        }
    }
}

// ---------------------------------------------------------------------------
// NUFFT via warp-level mma.sync (tf32): per (r, ec) a real GEMM
//   C[96 x 128] = A[96 x 128] . B^T,  A = [ey.re | -ey.im]  (k = y),
//   B rows: [x]=[img.re | img.im], [64+x]=[img.im | -img.re]
// (ex/ey swapped vs round 9 because scf pixel axis is now X-major.)
// grid (32 r, 4 ecg), block 256 (8 warps: m-split 2 x n-split 4).
// ---------------------------------------------------------------------------
#define KS       132                  // float stride (== 4 mod 32)
#define A_FLOATS (96 * KS)
#define B_FLOATS (128 * KS)

__global__ __launch_bounds__(256, 1)
void nufft_mma_kernel(const float* __restrict__ ur_list,   // [1,32,4]
                      const int*   __restrict__ sbin,      // [32]
                      float2* __restrict__ out)            // [96,4,32,3]
{
    extern __shared__ float sh[];
    float*  sA   = sh;                       // [96][KS]
    float*  sB   = sh + A_FLOATS;            // [128][KS], overlaid with C (t1)
    float2* sPar = (float2*)(sh + A_FLOATS + B_FLOATS);   // [96][2]

    const int r    = blockIdx.x;
    const int ecg  = blockIdx.y;
    const int tid  = threadIdx.x;
    const int lane = tid & 31;
    const int w    = tid >> 5;
    const int g    = lane >> 2;     // 0..7
    const int tg   = lane & 3;      // 0..3
    const int mg   = w >> 2;        // 0..1
    const int ng   = w & 3;         // 0..3

    // ---- build A (tf32): A[p][y] = ey.re, A[p][64+y] = -ey.im ----
    {
        const float2* gey = g_ey_ + (size_t)r * IMG * NPT;
        for (int i = tid; i < IMG * NPT; i += 256) {
            int y = i / NPT, p = i % NPT;
            float2 e = gey[i];
            sA[p * KS + y]      = tf32r(e.x);
            sA[p * KS + 64 + y] = tf32r(-e.y);
        }
    }

    const int kzr = sbin[r];
    const float u0 = ur_list[r * NSING + 0];
    const float u1 = ur_list[r * NSING + 1];
    const float u2 = ur_list[r * NSING + 2];
    const float u3 = ur_list[r * NSING + 3];

    const float* Abase = sA + (mg * 48 + g) * KS + tg;
    const float* Bbase = sB + (ng * 32 + g) * KS + tg;
    const float2* gex  = g_exp_ + (size_t)r * IMG * NPT;

    for (int it = 0; it < 3; ++it) {
        const int ec = ecg * 3 + it;
        const int e  = ec >> 2;
        const int c  = ec & 3;

        __syncthreads();

        // ---- build B for this ec (fused Ur mix); i = X*64+Y ----
        const float2* base = g_scf
            + ((size_t)(kzr * NCOIL + c) * 12 + e) * NPIX;
        for (int i = tid; i < NPIX; i += 256) {
            float2 s0 = base[i];
            float2 s1 = base[i + 3 * NPIX];
            float2 s2 = base[i + 6 * NPIX];
            float2 s3 = base[i + 9 * NPIX];
            float ar = fmaf(u0, s0.x, fmaf(u1, s1.x, fmaf(u2, s2.x, u3 * s3.x)));
            float ai = fmaf(u0, s0.y, fmaf(u1, s1.y, fmaf(u2, s2.y, u3 * s3.y)));
            int x = i >> 6, y = i & 63;
            float tar = tf32r(ar), tai = tf32r(ai);
            sB[x * KS + y]             = tar;
            sB[x * KS + 64 + y]        = tai;
            sB[(64 + x) * KS + y]      = tai;
            sB[(64 + x) * KS + 64 + y] = tf32r(-ar);
        }
        __syncthreads();

        // ---- mma mainloop: K = 128 in 16 k8 steps ----
        float d[3][4][4];
#pragma unroll
        for (int mt = 0; mt < 3; ++mt)
#pragma unroll
            for (int nt = 0; nt < 4; ++nt)
#pragma unroll
                for (int q = 0; q < 4; ++q) d[mt][nt][q] = 0.f;

#pragma unroll
        for (int k0 = 0; k0 < 128; k0 += 8) {
            uint32_t a[3][4], b[4][2];
#pragma unroll
            for (int mt = 0; mt < 3; ++mt) {
                const float* ap = Abase + mt * 16 * KS + k0;
                a[mt][0] = __float_as_uint(ap[0]);
                a[mt][1] = __float_as_uint(ap[8 * KS]);
                a[mt][2] = __float_as_uint(ap[4]);
                a[mt][3] = __float_as_uint(ap[8 * KS + 4]);
            }
#pragma unroll
            for (int nt = 0; nt < 4; ++nt) {
                const float* bp = Bbase + nt * 8 * KS + k0;
                b[nt][0] = __float_as_uint(bp[0]);
                b[nt][1] = __float_as_uint(bp[4]);
            }
#pragma unroll
            for (int mt = 0; mt < 3; ++mt)
#pragma unroll
                for (int nt = 0; nt < 4; ++nt)
                    mma_tf32(d[mt][nt], a[mt], b[nt]);
        }

        __syncthreads();   // everyone done reading sB -> overlay C

        // ---- store C (t1) into sB overlay: t1[p][ncol], rows 0..95 ----
#pragma unroll
        for (int mt = 0; mt < 3; ++mt) {
#pragma unroll
            for (int nt = 0; nt < 4; ++nt) {
                int p = mg * 48 + mt * 16 + g;
                int n = ng * 32 + nt * 8 + 2 * tg;
                sB[p * KS + n]           = d[mt][nt][0];
                sB[p * KS + n + 1]       = d[mt][nt][1];
                sB[(p + 8) * KS + n]     = d[mt][nt][2];
                sB[(p + 8) * KS + n + 1] = d[mt][nt][3];
            }
        }
        __syncthreads();

        // ---- ex contraction: thread (p, h) handles x in [32h, 32h+32) ----
        if (tid < 192) {
            int p = tid % 96, h = tid / 96;
            float orr = 0.f, oii = 0.f;
            const float* rowp = sB + p * KS;
#pragma unroll 8
            for (int x = 32 * h; x < 32 * h + 32; ++x) {
                float tr = rowp[x];
                float ti = rowp[64 + x];
                float2 ex = gex[x * NPT + p];
                orr = fmaf(tr,  ex.x, orr);
                orr = fmaf(-ti, ex.y, orr);
                oii = fmaf(tr,  ex.y, oii);
                oii = fmaf(ti,  ex.x, oii);
            }
            sPar[p * 2 + h] = make_float2(orr, oii);
        }
        __syncthreads();

        if (tid < NPT) {
            float2 v0 = sPar[tid * 2 + 0];
            float2 v1 = sPar[tid * 2 + 1];
            out[((tid * NCOIL + c) * NRO + r) * NECHO + e]
                = make_float2(v0.x + v1.x, v0.y + v1.y);
        }
    }
}

// ---------------------------------------------------------------------------
extern "C" void kernel_launch(void* const* d_in, const int* in_sizes, int n_in,
                              void* d_out, int out_size)
{
    const float* singulars = (const float*)d_in[0];
    const float* smap      = (const float*)d_in[1];
    const float* ktraj     = (const float*)d_in[2];
    const float* ur_list   = (const float*)d_in[3];
    const int*   sbin      = (const int*)d_in[4];
    // d_in[5] = dc (unused by the forward reference)

    float2* out = (float2*)d_out;

    const int smemNufft = (A_FLOATS + B_FLOATS) * (int)sizeof(float)
                        + 96 * 2 * (int)sizeof(float2);    // ~117KB
    cudaFuncSetAttribute(nufft_mma_kernel,
                         cudaFuncAttributeMaxDynamicSharedMemorySize, smemNufft);

    transpose_kernel<<<dim3(16, 16), 256>>>(singulars);
    exgen_kernel<<<NRO, 384>>>(ktraj);
    stageA_kernel<<<dim3(16, 48), 256>>>(smap);
    nufft_mma_kernel<<<dim3(NRO, 4), 256, smemNufft>>>(ur_list, sbin, out);
}

// round 11
// speedup vs baseline: 1.1237x; 1.1237x over previous
#include <cuda_runtime.h>
#include <math.h>
#include <stdint.h>

#define IMG    64
#define NSLICE 16
#define NCOIL  4
#define NSING  4
#define NECHO  3
#define NRO    32
#define NPT    96
#define NEC    (NECHO * NCOIL)   // 12
#define NPIX   (IMG * IMG)       // 4096

// scf[kz][c][ne=n*3+e][pix]  (25 MB)   pixel index = X*64+Y (X major)
__device__ float2 g_scf[NSLICE * NCOIL * (NSING * NECHO) * NPIX];
// transposed singulars: tsing[ne][z][pix]  (6.3 MB)
__device__ float2 g_tsing[(NSING * NECHO) * NSLICE * NPIX];
// phase tables [r][x|y][p]
__device__ float2 g_exp_[NRO * IMG * NPT];   // exp(-i*w0*(x-32)) = (re, im)
__device__ float2 g_ey_[NRO * IMG * NPT];    // exp(-i*w1*(y-32))

// ---------------------------------------------------------------------------
// helpers
// ---------------------------------------------------------------------------
__device__ __forceinline__ float tf32r(float f) {
    uint32_t u;
    asm("cvt.rn.tf32.f32 %0, %1;" : "=r"(u) : "f"(f));
    return __uint_as_float(u);
}
__device__ __forceinline__ void mma_tf32(float* d, const uint32_t* a, const uint32_t* b) {
    asm volatile(
        "mma.sync.aligned.m16n8k8.row.col.f32.tf32.tf32.f32 "
        "{%0,%1,%2,%3}, {%4,%5,%6,%7}, {%8,%9}, {%0,%1,%2,%3};"
        : "+f"(d[0]), "+f"(d[1]), "+f"(d[2]), "+f"(d[3])
        : "r"(a[0]), "r"(a[1]), "r"(a[2]), "r"(a[3]), "r"(b[0]), "r"(b[1]));
}

// ---------------------------------------------------------------------------
// Transpose: singulars [pix][z][ne]{2} -> g_tsing [ne][z][pix]{2}
// ---------------------------------------------------------------------------
__global__ __launch_bounds__(256)
void transpose_kernel(const float* __restrict__ singulars)   // [64,64,16,4,3,2]
{
    __shared__ float sS[256][25];   // 24 floats + pad
    const int z  = blockIdx.y;
    const int pb = blockIdx.x * 256;
    const int t  = threadIdx.x;

    const float4* src = (const float4*)(singulars + (size_t)(pb + t) * 384 + z * 24);
#pragma unroll
    for (int q = 0; q < 6; ++q) {
        float4 f = src[q];
        sS[t][4 * q + 0] = f.x; sS[t][4 * q + 1] = f.y;
        sS[t][4 * q + 2] = f.z; sS[t][4 * q + 3] = f.w;
    }
    __syncthreads();

#pragma unroll
    for (int j = 0; j < 12; ++j) {
        g_tsing[((size_t)j * NSLICE + z) * NPIX + pb + t]
            = make_float2(sS[t][2 * j], sS[t][2 * j + 1]);
    }
}

// ---------------------------------------------------------------------------
// Stage A (e-split): z-DFT of sign(z)*tsing*smap for one (c, ne) per block.
// smap staged through shared (coalesced) to kill the 32-line replay pattern.
// grid (16 pixblk, 48 = c + 4*ne), block 256, 3 blocks/SM.
// ---------------------------------------------------------------------------
__global__ __launch_bounds__(256, 3)
void stageA_kernel(const float* __restrict__ smap)   // [4,64,64,16,2]
{
    __shared__ float2 W[NSLICE][NSLICE];   // W[z][kz]
    __shared__ float2 sSm[256][17];        // staged smap tile, padded

    const int pixb = blockIdx.x * 256;
    const int pix  = pixb + threadIdx.x;
    const int j    = blockIdx.y;
    const int c    = j & 3;
    const int ne   = j >> 2;               // n*3+e

    {
        int z = threadIdx.x >> 4, kz = threadIdx.x & 15;
        float ang = -(2.0f * (float)M_PI / (float)NSLICE) * (float)(kz * z);
        float s, co; sincosf(ang, &s, &co);
        float sgn = (z & 1) ? -1.0f : 1.0f;
        W[z][kz] = make_float2(co * sgn, s * sgn);
    }
    // stage smap tile: [256 pix][16 z], fully coalesced global reads
    {
        const float2* smap2 = (const float2*)(smap) + ((size_t)c * NPIX + pixb) * NSLICE;
        for (int i = threadIdx.x; i < 256 * NSLICE; i += 256) {
            sSm[i >> 4][i & 15] = smap2[i];
        }
    }
    __syncthreads();

    const float2* vsrc = g_tsing + (size_t)ne * NSLICE * NPIX + pix;

    float accr[NSLICE], acci[NSLICE];
#pragma unroll
    for (int kz = 0; kz < NSLICE; ++kz) { accr[kz] = 0.f; acci[kz] = 0.f; }

#pragma unroll
    for (int z = 0; z < NSLICE; ++z) {
        float2 v  = vsrc[(size_t)z * NPIX];
        float2 sm = sSm[threadIdx.x][z];
        float tr = v.x * sm.x - v.y * sm.y;
        float ti = v.x * sm.y + v.y * sm.x;
#pragma unroll
        for (int kz = 0; kz < NSLICE; ++kz) {
            float2 w = W[z][kz];
            accr[kz] = fmaf(tr, w.x, accr[kz]);
            accr[kz] = fmaf(-ti, w.y, accr[kz]);
            acci[kz] = fmaf(tr, w.y, acci[kz]);
            acci[kz] = fmaf(ti, w.x, acci[kz]);
        }
    }

#pragma unroll
    for (int kz = 0; kz < NSLICE; ++kz) {
        g_scf[(((size_t)kz * NCOIL + c) * 12 + ne) * NPIX + pix]
            = make_float2(accr[kz], acci[kz]);
    }
}

// ---------------------------------------------------------------------------
// Phase tables, parallel over 4 segments of 16. grid 32, block 384.
// ---------------------------------------------------------------------------
__global__ __launch_bounds__(384)
void exgen_kernel(const float* __restrict__ ktraj)   // [1,32,96,2]
{
    const int r = blockIdx.x;
    const int p = threadIdx.x % NPT;
    const int g = threadIdx.x / NPT;       // 0..3, 16 steps each
    const float w0 = ktraj[(r * NPT + p) * 2 + 0];
    const float w1 = ktraj[(r * NPT + p) * 2 + 1];

    {
        float s, c; sincosf(w0, &s, &c);                      // step exp(-i*w0)
        float pr, pi; sincosf(w0 * (32.0f - g * 16.0f), &pi, &pr);
#pragma unroll 4
        for (int jj = 0; jj < 16; ++jj) {
            int x = g * 16 + jj;
            g_exp_[((size_t)r * IMG + x) * NPT + p] = make_float2(pr, pi);
            float t = pr;
            pr = fmaf(pr, c, pi * s);
            pi = fmaf(pi, c, -(t * s));
        }
    }
    {
        float s, c; sincosf(w1, &s, &c);
        float pr, pi; sincosf(w1 * (32.0f - g * 16.0f), &pi, &pr);
#pragma unroll 4
        for (int jj = 0; jj < 16; ++jj) {
            int y = g * 16 + jj;
            g_ey_[((size_t)r * IMG + y) * NPT + p] = make_float2(pr, pi);
            float t = pr;
            pr = fmaf(pr, c, pi * s);
            pi = fmaf(pi, c, -(t * s));
        }
    }
}

// ---------------------------------------------------------------------------
// NUFFT via warp-level mma.sync (tf32): per (r, ec) a real GEMM
//   C[96 x 128] = A[96 x 128] . B^T,  A = [ey.re | -ey.im]  (k = y),
//   B rows: [x]=[img.re | img.im], [64+x]=[img.im | -img.re]
// grid (32 r, 4 ecg), block 512 (16 warps: m-split 2 x n-split 8).
// Each warp: 3 m-tiles (m16) x 2 n-tiles (n8), K = 16 x k8.
// ---------------------------------------------------------------------------
#define KS       132                  // float stride (== 4 mod 32)
#define A_FLOATS (96 * KS)
#define B_FLOATS (128 * KS)

__global__ __launch_bounds__(512, 1)
void nufft_mma_kernel(const float* __restrict__ ur_list,   // [1,32,4]
                      const int*   __restrict__ sbin,      // [32]
                      float2* __restrict__ out)            // [96,4,32,3]
{
    extern __shared__ float sh[];
    float*  sA   = sh;                       // [96][KS]
    float*  sB   = sh + A_FLOATS;            // [128][KS], overlaid with C (t1)
    float2* sPar = (float2*)(sh + A_FLOATS + B_FLOATS);   // [96][4]

    const int r    = blockIdx.x;
    const int ecg  = blockIdx.y;
    const int tid  = threadIdx.x;
    const int lane = tid & 31;
    const int w    = tid >> 5;      // 0..15
    const int g    = lane >> 2;     // 0..7
    const int tg   = lane & 3;      // 0..3
    const int mg   = w >> 3;        // 0..1  (m-rows 48*mg ..)
    const int ng   = w & 7;         // 0..7  (n-cols 16*ng ..)

    // ---- build A (tf32): A[p][y] = ey.re, A[p][64+y] = -ey.im ----
    {
        const float2* gey = g_ey_ + (size_t)r * IMG * NPT;
        for (int i = tid; i < IMG * NPT; i += 512) {
            int y = i / NPT, p = i % NPT;
            float2 e = gey[i];
            sA[p * KS + y]      = tf32r(e.x);
            sA[p * KS + 64 + y] = tf32r(-e.y);
        }
    }

    const int kzr = sbin[r];
    const float u0 = ur_list[r * NSING + 0];
    const float u1 = ur_list[r * NSING + 1];
    const float u2 = ur_list[r * NSING + 2];
    const float u3 = ur_list[r * NSING + 3];

    const float* Abase = sA + (mg * 48 + g) * KS + tg;
    const float* Bbase = sB + (ng * 16 + g) * KS + tg;
    const float2* gex  = g_exp_ + (size_t)r * IMG * NPT;

    for (int it = 0; it < 3; ++it) {
        const int ec = ecg * 3 + it;
        const int e  = ec >> 2;
        const int c  = ec & 3;

        __syncthreads();   // prior epilogue readers of sB/C done (A build on it==0)

        // ---- build B for this ec (fused Ur mix); i = X*64+Y ----
        const float2* base = g_scf
            + ((size_t)(kzr * NCOIL + c) * 12 + e) * NPIX;
        for (int i = tid; i < NPIX; i += 512) {
            float2 s0 = base[i];
            float2 s1 = base[i + 3 * NPIX];
            float2 s2 = base[i + 6 * NPIX];
            float2 s3 = base[i + 9 * NPIX];
            float ar = fmaf(u0, s0.x, fmaf(u1, s1.x, fmaf(u2, s2.x, u3 * s3.x)));
            float ai = fmaf(u0, s0.y, fmaf(u1, s1.y, fmaf(u2, s2.y, u3 * s3.y)));
            int x = i >> 6, y = i & 63;
            float tar = tf32r(ar), tai = tf32r(ai);
            sB[x * KS + y]             = tar;
            sB[x * KS + 64 + y]        = tai;
            sB[(64 + x) * KS + y]      = tai;
            sB[(64 + x) * KS + 64 + y] = tf32r(-ar);
        }
        __syncthreads();

        // ---- mma mainloop: K = 128 in 16 k8 steps ----
        float d[3][2][4];
#pragma unroll
        for (int mt = 0; mt < 3; ++mt)
#pragma unroll
            for (int nt = 0; nt < 2; ++nt)
#pragma unroll
                for (int q = 0; q < 4; ++q) d[mt][nt][q] = 0.f;

#pragma unroll
        for (int k0 = 0; k0 < 128; k0 += 8) {
            uint32_t a[3][4], b[2][2];
#pragma unroll
            for (int mt = 0; mt < 3; ++mt) {
                const float* ap = Abase + mt * 16 * KS + k0;
                a[mt][0] = __float_as_uint(ap[0]);
                a[mt][1] = __float_as_uint(ap[8 * KS]);
                a[mt][2] = __float_as_uint(ap[4]);
                a[mt][3] = __float_as_uint(ap[8 * KS + 4]);
            }
#pragma unroll
            for (int nt = 0; nt < 2; ++nt) {
                const float* bp = Bbase + nt * 8 * KS + k0;
                b[nt][0] = __float_as_uint(bp[0]);
                b[nt][1] = __float_as_uint(bp[4]);
            }
#pragma unroll
            for (int mt = 0; mt < 3; ++mt)
#pragma unroll
                for (int nt = 0; nt < 2; ++nt)
                    mma_tf32(d[mt][nt], a[mt], b[nt]);
        }

        __syncthreads();   // everyone done reading sB -> overlay C

        // ---- store C (t1) into sB overlay: t1[p][ncol], rows 0..95 ----
#pragma unroll
        for (int mt = 0; mt < 3; ++mt) {
#pragma unroll
            for (int nt = 0; nt < 2; ++nt) {
                int p = mg * 48 + mt * 16 + g;
                int n = ng * 16 + nt * 8 + 2 * tg;
                sB[p * KS + n]           = d[mt][nt][0];
                sB[p * KS + n + 1]       = d[mt][nt][1];
                sB[(p + 8) * KS + n]     = d[mt][nt][2];
                sB[(p + 8) * KS + n + 1] = d[mt][nt][3];
            }
        }
        __syncthreads();

        // ---- ex contraction: thread (p, h) handles x in [16h, 16h+16) ----
        if (tid < 384) {
            int p = tid % 96, h = tid / 96;          // h 0..3
            float orr = 0.f, oii = 0.f;
            const float* rowp = sB + p * KS;
#pragma unroll 8
            for (int x = 16 * h; x < 16 * h + 16; ++x) {
                float tr = rowp[x];
                float ti = rowp[64 + x];
                float2 ex = gex[x * NPT + p];
                orr = fmaf(tr,  ex.x, orr);
                orr = fmaf(-ti, ex.y, orr);
                oii = fmaf(tr,  ex.y, oii);
                oii = fmaf(ti,  ex.x, oii);
            }
            sPar[p * 4 + h] = make_float2(orr, oii);
        }
        __syncthreads();

        if (tid < NPT) {
            float2 v0 = sPar[tid * 4 + 0];
            float2 v1 = sPar[tid * 4 + 1];
            float2 v2 = sPar[tid * 4 + 2];
            float2 v3 = sPar[tid * 4 + 3];
            out[((tid * NCOIL + c) * NRO + r) * NECHO + e]
                = make_float2(v0.x + v1.x + v2.x + v3.x,
                              v0.y + v1.y + v2.y + v3.y);
        }
    }
}

// ---------------------------------------------------------------------------
extern "C" void kernel_launch(void* const* d_in, const int* in_sizes, int n_in,
                              void* d_out, int out_size)
{
    const float* singulars = (const float*)d_in[0];
    const float* smap      = (const float*)d_in[1];
    const float* ktraj     = (const float*)d_in[2];
    const float* ur_list   = (const float*)d_in[3];
    const int*   sbin      = (const int*)d_in[4];
    // d_in[5] = dc (unused by the forward reference)

    float2* out = (float2*)d_out;

    const int smemNufft = (A_FLOATS + B_FLOATS) * (int)sizeof(float)
                        + 96 * 4 * (int)sizeof(float2);    // ~118.5KB
    cudaFuncSetAttribute(nufft_mma_kernel,
                         cudaFuncAttributeMaxDynamicSharedMemorySize, smemNufft);

    transpose_kernel<<<dim3(16, 16), 256>>>(singulars);
    exgen_kernel<<<NRO, 384>>>(ktraj);
    stageA_kernel<<<dim3(16, 48), 256>>>(smap);
    nufft_mma_kernel<<<dim3(NRO, 4), 512, smemNufft>>>(ur_list, sbin, out);
}

// round 12
// speedup vs baseline: 1.2256x; 1.0907x over previous
#include <cuda_runtime.h>
#include <math.h>
#include <stdint.h>

#define IMG    64
#define NSLICE 16
#define NCOIL  4
#define NSING  4
#define NECHO  3
#define NRO    32
#define NPT    96
#define NEC    (NECHO * NCOIL)   // 12
#define NPIX   (IMG * IMG)       // 4096

// scf[kz][c][ne=n*3+e][pix]  (25 MB)   pixel index = X*64+Y (X major)
__device__ float2 g_scf[NSLICE * NCOIL * (NSING * NECHO) * NPIX];
// transposed singulars: tsing[ne][z][pix]  (6.3 MB)
__device__ float2 g_tsing[(NSING * NECHO) * NSLICE * NPIX];
// phase tables [r][x|y][p]
__device__ float2 g_exp_[NRO * IMG * NPT];   // exp(-i*w0*(x-32)) = (re, im)
__device__ float2 g_ey_[NRO * IMG * NPT];    // exp(-i*w1*(y-32))

// ---------------------------------------------------------------------------
// helpers
// ---------------------------------------------------------------------------
__device__ __forceinline__ float tf32r(float f) {
    uint32_t u;
    asm("cvt.rn.tf32.f32 %0, %1;" : "=r"(u) : "f"(f));
    return __uint_as_float(u);
}
__device__ __forceinline__ void mma_tf32(float* d, const uint32_t* a, const uint32_t* b) {
    asm volatile(
        "mma.sync.aligned.m16n8k8.row.col.f32.tf32.tf32.f32 "
        "{%0,%1,%2,%3}, {%4,%5,%6,%7}, {%8,%9}, {%0,%1,%2,%3};"
        : "+f"(d[0]), "+f"(d[1]), "+f"(d[2]), "+f"(d[3])
        : "r"(a[0]), "r"(a[1]), "r"(a[2]), "r"(a[3]), "r"(b[0]), "r"(b[1]));
}

// ---------------------------------------------------------------------------
// Transpose: singulars [pix][z][ne]{2} -> g_tsing [ne][z][pix]{2}
// ---------------------------------------------------------------------------
__global__ __launch_bounds__(256)
void transpose_kernel(const float* __restrict__ singulars)   // [64,64,16,4,3,2]
{
    __shared__ float sS[256][25];   // 24 floats + pad
    const int z  = blockIdx.y;
    const int pb = blockIdx.x * 256;
    const int t  = threadIdx.x;

    const float4* src = (const float4*)(singulars + (size_t)(pb + t) * 384 + z * 24);
#pragma unroll
    for (int q = 0; q < 6; ++q) {
        float4 f = src[q];
        sS[t][4 * q + 0] = f.x; sS[t][4 * q + 1] = f.y;
        sS[t][4 * q + 2] = f.z; sS[t][4 * q + 3] = f.w;
    }
    __syncthreads();

#pragma unroll
    for (int j = 0; j < 12; ++j) {
        g_tsing[((size_t)j * NSLICE + z) * NPIX + pb + t]
            = make_float2(sS[t][2 * j], sS[t][2 * j + 1]);
    }
}

// ---------------------------------------------------------------------------
// Stage A (radix-2 DIF over z): for one (c, ne) per block,
//   S(kz) = sum_z sign(z) w16^(kz z) t(z),  t = tsing*smap.
// Even kz=2m: DFT8 of a(z0)=t(z0)+t(z0+8) with table sign(z0)*w8^(m z0).
// Odd  kz=2m+1: DFT8 of b = (t(z0)-t(z0+8))*sign(z0)*w16^(z0) with w8^(m z0).
// grid (16 pixblk, 48), block 256, 3 blocks/SM.
// ---------------------------------------------------------------------------
__global__ __launch_bounds__(256, 3)
void stageA_kernel(const float* __restrict__ smap)   // [4,64,64,16,2]
{
    __shared__ float2 T8[8][8];     // w8^(m z0)
    __shared__ float2 T8s[8][8];    // sign(z0) * w8^(m z0)
    __shared__ float2 tws[8];       // sign(z0) * w16^(z0)
    __shared__ float2 sSm[256][17]; // staged smap tile, padded

    const int pixb = blockIdx.x * 256;
    const int t    = threadIdx.x;
    const int pix  = pixb + t;
    const int j    = blockIdx.y;
    const int c    = j & 3;
    const int ne   = j >> 2;               // n*3+e

    if (t < 64) {
        int z0 = t >> 3, m = t & 7;
        float ang = -(2.0f * (float)M_PI / 8.0f) * (float)(m * z0);
        float s, co; sincosf(ang, &s, &co);
        T8[z0][m] = make_float2(co, s);
        float sgn = (z0 & 1) ? -1.0f : 1.0f;
        T8s[z0][m] = make_float2(co * sgn, s * sgn);
    }
    if (t < 8) {
        float ang = -(2.0f * (float)M_PI / 16.0f) * (float)t;
        float s, co; sincosf(ang, &s, &co);
        float sgn = (t & 1) ? -1.0f : 1.0f;
        tws[t] = make_float2(co * sgn, s * sgn);
    }
    // stage smap tile: [256 pix][16 z], coalesced global reads
    {
        const float2* smap2 = (const float2*)(smap) + ((size_t)c * NPIX + pixb) * NSLICE;
        for (int i = t; i < 256 * NSLICE; i += 256)
            sSm[i >> 4][i & 15] = smap2[i];
    }
    __syncthreads();

    const float2* vsrc = g_tsing + (size_t)ne * NSLICE * NPIX + pix;

    float aEr[8], aEi[8], aOr[8], aOi[8];
#pragma unroll
    for (int m = 0; m < 8; ++m) { aEr[m] = 0.f; aEi[m] = 0.f; aOr[m] = 0.f; aOi[m] = 0.f; }

#pragma unroll
    for (int z0 = 0; z0 < 8; ++z0) {
        float2 v0 = vsrc[(size_t)z0 * NPIX];
        float2 v8 = vsrc[(size_t)(z0 + 8) * NPIX];
        float2 s0 = sSm[t][z0];
        float2 s8 = sSm[t][z0 + 8];

        float t0r = v0.x * s0.x - v0.y * s0.y;
        float t0i = v0.x * s0.y + v0.y * s0.x;
        float t8r = v8.x * s8.x - v8.y * s8.y;
        float t8i = v8.x * s8.y + v8.y * s8.x;

        float ar  = t0r + t8r, ai = t0i + t8i;     // even branch
        float bpr = t0r - t8r, bpi = t0i - t8i;    // odd branch (pre-twiddle)
        float2 tw = tws[z0];
        float br = bpr * tw.x - bpi * tw.y;
        float bi = bpr * tw.y + bpi * tw.x;

#pragma unroll
        for (int m = 0; m < 8; ++m) {
            float2 wE = T8s[z0][m];
            aEr[m] = fmaf(ar, wE.x, aEr[m]);  aEr[m] = fmaf(-ai, wE.y, aEr[m]);
            aEi[m] = fmaf(ar, wE.y, aEi[m]);  aEi[m] = fmaf( ai, wE.x, aEi[m]);
            float2 wO = T8[z0][m];
            aOr[m] = fmaf(br, wO.x, aOr[m]);  aOr[m] = fmaf(-bi, wO.y, aOr[m]);
            aOi[m] = fmaf(br, wO.y, aOi[m]);  aOi[m] = fmaf( bi, wO.x, aOi[m]);
        }
    }

#pragma unroll
    for (int m = 0; m < 8; ++m) {
        g_scf[(((size_t)(2 * m) * NCOIL + c) * 12 + ne) * NPIX + pix]
            = make_float2(aEr[m], aEi[m]);
        g_scf[(((size_t)(2 * m + 1) * NCOIL + c) * 12 + ne) * NPIX + pix]
            = make_float2(aOr[m], aOi[m]);
    }
}

// ---------------------------------------------------------------------------
// Phase tables, parallel over 4 segments of 16. grid 32, block 384.
// ---------------------------------------------------------------------------
__global__ __launch_bounds__(384)
void exgen_kernel(const float* __restrict__ ktraj)   // [1,32,96,2]
{
    const int r = blockIdx.x;
    const int p = threadIdx.x % NPT;
    const int g = threadIdx.x / NPT;       // 0..3, 16 steps each
    const float w0 = ktraj[(r * NPT + p) * 2 + 0];
    const float w1 = ktraj[(r * NPT + p) * 2 + 1];

    {
        float s, c; sincosf(w0, &s, &c);                      // step exp(-i*w0)
        float pr, pi; sincosf(w0 * (32.0f - g * 16.0f), &pi, &pr);
#pragma unroll 4
        for (int jj = 0; jj < 16; ++jj) {
            int x = g * 16 + jj;
            g_exp_[((size_t)r * IMG + x) * NPT + p] = make_float2(pr, pi);
            float t = pr;
            pr = fmaf(pr, c, pi * s);
            pi = fmaf(pi, c, -(t * s));
        }
    }
    {
        float s, c; sincosf(w1, &s, &c);
        float pr, pi; sincosf(w1 * (32.0f - g * 16.0f), &pi, &pr);
#pragma unroll 4
        for (int jj = 0; jj < 16; ++jj) {
            int y = g * 16 + jj;
            g_ey_[((size_t)r * IMG + y) * NPT + p] = make_float2(pr, pi);
            float t = pr;
            pr = fmaf(pr, c, pi * s);
            pi = fmaf(pi, c, -(t * s));
        }
    }
}

// ---------------------------------------------------------------------------
// NUFFT via warp-level mma.sync (tf32), software-pipelined:
//   C[96 x 128] = A[96 x 128] . B^T,  A = [ey.re | -ey.im]  (k = y),
//   B rows: [x]=[img.re | img.im], [64+x]=[img.im | -img.re]
// Double-buffered B; next ec's g_scf loads + Ur mix prefetched into registers
// before the current mma mainloop (LDG latency hidden behind tensor work).
// grid (32 r, 4 ecg), block 512 (16 warps: m-split 2 x n-split 8).
// ---------------------------------------------------------------------------
#define KS       132                  // float stride (== 4 mod 32)
#define A_FLOATS (96 * KS)
#define B_FLOATS (128 * KS)

__global__ __launch_bounds__(512, 1)
void nufft_mma_kernel(const float* __restrict__ ur_list,   // [1,32,4]
                      const int*   __restrict__ sbin,      // [32]
                      float2* __restrict__ out)            // [96,4,32,3]
{
    extern __shared__ float sh[];
    float*  sA   = sh;                        // [96][KS]
    float*  sB0  = sh + A_FLOATS;             // [128][KS]
    float*  sB1  = sB0 + B_FLOATS;            // [128][KS]
    float2* sPar = (float2*)(sB1 + B_FLOATS); // [96][4]

    const int r    = blockIdx.x;
    const int ecg  = blockIdx.y;
    const int tid  = threadIdx.x;
    const int lane = tid & 31;
    const int w    = tid >> 5;      // 0..15
    const int g    = lane >> 2;     // 0..7
    const int tg   = lane & 3;      // 0..3
    const int mg   = w >> 3;        // 0..1  (m-rows 48*mg ..)
    const int ng   = w & 7;         // 0..7  (n-cols 16*ng ..)

    // ---- build A (tf32): A[p][y] = ey.re, A[p][64+y] = -ey.im ----
    {
        const float2* gey = g_ey_ + (size_t)r * IMG * NPT;
        for (int i = tid; i < IMG * NPT; i += 512) {
            int y = i / NPT, p = i % NPT;
            float2 e = gey[i];
            sA[p * KS + y]      = tf32r(e.x);
            sA[p * KS + 64 + y] = tf32r(-e.y);
        }
    }

    const int kzr = sbin[r];
    const float u0 = ur_list[r * NSING + 0];
    const float u1 = ur_list[r * NSING + 1];
    const float u2 = ur_list[r * NSING + 2];
    const float u3 = ur_list[r * NSING + 3];

    // per-ec g_scf base
    const float2* bases[3];
#pragma unroll
    for (int it = 0; it < 3; ++it) {
        int ec = ecg * 3 + it;
        bases[it] = g_scf + ((size_t)(kzr * NCOIL + (ec & 3)) * 12 + (ec >> 2)) * NPIX;
    }

    float mr[8], mi[8];   // prefetched+mixed image values for next B

    // load + Ur-mix one ec's image into registers (32 LDG.64 in flight)
#define LOAD_MIX(IT)                                                      \
    {                                                                     \
        const float2* base = bases[IT];                                   \
        _Pragma("unroll")                                                 \
        for (int jj = 0; jj < 8; ++jj) {                                  \
            int i = tid + jj * 512;                                       \
            float2 s0 = base[i];                                          \
            float2 s1 = base[i + 3 * NPIX];                               \
            float2 s2 = base[i + 6 * NPIX];                               \
            float2 s3 = base[i + 9 * NPIX];                               \
            mr[jj] = fmaf(u0, s0.x, fmaf(u1, s1.x, fmaf(u2, s2.x, u3 * s3.x))); \
            mi[jj] = fmaf(u0, s0.y, fmaf(u1, s1.y, fmaf(u2, s2.y, u3 * s3.y))); \
        }                                                                 \
    }

#define STORE_B(BUF)                                                      \
    {                                                                     \
        float* dst = (BUF);                                               \
        _Pragma("unroll")                                                 \
        for (int jj = 0; jj < 8; ++jj) {                                  \
            int i = tid + jj * 512;                                       \
            int x = i >> 6, y = i & 63;                                   \
            float tar = tf32r(mr[jj]), tai = tf32r(mi[jj]);               \
            dst[x * KS + y]             = tar;                            \
            dst[x * KS + 64 + y]        = tai;                            \
            dst[(64 + x) * KS + y]      = tai;                            \
            dst[(64 + x) * KS + 64 + y] = tf32r(-mr[jj]);                 \
        }                                                                 \
    }

    // prologue
    LOAD_MIX(0);
    __syncthreads();          // A visible
    STORE_B(sB0);
    LOAD_MIX(1);              // prefetch ec1 (LDGs in flight through mma(0))
    __syncthreads();          // B0 visible

    const float* AbaseT = sA + (mg * 48 + g) * KS + tg;
    const float2* gex   = g_exp_ + (size_t)r * IMG * NPT;

    for (int it = 0; it < 3; ++it) {
        const int ec = ecg * 3 + it;
        const int e  = ec >> 2;
        const int c  = ec & 3;
        float* bufc = (it & 1) ? sB1 : sB0;
        float* bufn = (it & 1) ? sB0 : sB1;
        const float* Bbase = bufc + (ng * 16 + g) * KS + tg;

        // ---- mma mainloop: K = 128 in 16 k8 steps ----
        float d[3][2][4];
#pragma unroll
        for (int mt = 0; mt < 3; ++mt)
#pragma unroll
            for (int nt = 0; nt < 2; ++nt)
#pragma unroll
                for (int q = 0; q < 4; ++q) d[mt][nt][q] = 0.f;

#pragma unroll
        for (int k0 = 0; k0 < 128; k0 += 8) {
            uint32_t a[3][4], b[2][2];
#pragma unroll
            for (int mt = 0; mt < 3; ++mt) {
                const float* ap = AbaseT + mt * 16 * KS + k0;
                a[mt][0] = __float_as_uint(ap[0]);
                a[mt][1] = __float_as_uint(ap[8 * KS]);
                a[mt][2] = __float_as_uint(ap[4]);
                a[mt][3] = __float_as_uint(ap[8 * KS + 4]);
            }
#pragma unroll
            for (int nt = 0; nt < 2; ++nt) {
                const float* bp = Bbase + nt * 8 * KS + k0;
                b[nt][0] = __float_as_uint(bp[0]);
                b[nt][1] = __float_as_uint(bp[4]);
            }
#pragma unroll
            for (int mt = 0; mt < 3; ++mt)
#pragma unroll
                for (int nt = 0; nt < 2; ++nt)
                    mma_tf32(d[mt][nt], a[mt], b[nt]);
        }

        // write next B while mma results settle (prefetched regs)
        if (it < 2) STORE_B(bufn);
        if (it < 1) LOAD_MIX(2);     // prefetch last ec

        __syncthreads();   // mma reads of bufc done; bufn stores visible later

        // ---- store C (t1) into bufc overlay: t1[p][ncol], rows 0..95 ----
#pragma unroll
        for (int mt = 0; mt < 3; ++mt) {
#pragma unroll
            for (int nt = 0; nt < 2; ++nt) {
                int p = mg * 48 + mt * 16 + g;
                int n = ng * 16 + nt * 8 + 2 * tg;
                bufc[p * KS + n]           = d[mt][nt][0];
                bufc[p * KS + n + 1]       = d[mt][nt][1];
                bufc[(p + 8) * KS + n]     = d[mt][nt][2];
                bufc[(p + 8) * KS + n + 1] = d[mt][nt][3];
            }
        }
        __syncthreads();

        // ---- ex contraction: thread (p, h) handles x in [16h, 16h+16) ----
        if (tid < 384) {
            int p = tid % 96, h = tid / 96;          // h 0..3
            float orr = 0.f, oii = 0.f;
            const float* rowp = bufc + p * KS;
#pragma unroll 8
            for (int x = 16 * h; x < 16 * h + 16; ++x) {
                float tr = rowp[x];
                float ti = rowp[64 + x];
                float2 ex = gex[x * NPT + p];
                orr = fmaf(tr,  ex.x, orr);
                orr = fmaf(-ti, ex.y, orr);
                oii = fmaf(tr,  ex.y, oii);
                oii = fmaf(ti,  ex.x, oii);
            }
            sPar[p * 4 + h] = make_float2(orr, oii);
        }
        __syncthreads();

        if (tid < NPT) {
            float2 v0 = sPar[tid * 4 + 0];
            float2 v1 = sPar[tid * 4 + 1];
            float2 v2 = sPar[tid * 4 + 2];
            float2 v3 = sPar[tid * 4 + 3];
            out[((tid * NCOIL + c) * NRO + r) * NECHO + e]
                = make_float2(v0.x + v1.x + v2.x + v3.x,
                              v0.y + v1.y + v2.y + v3.y);
        }
    }
#undef LOAD_MIX
#undef STORE_B
}

// ---------------------------------------------------------------------------
extern "C" void kernel_launch(void* const* d_in, const int* in_sizes, int n_in,
                              void* d_out, int out_size)
{
    const float* singulars = (const float*)d_in[0];
    const float* smap      = (const float*)d_in[1];
    const float* ktraj     = (const float*)d_in[2];
    const float* ur_list   = (const float*)d_in[3];
    const int*   sbin      = (const int*)d_in[4];
    // d_in[5] = dc (unused by the forward reference)

    float2* out = (float2*)d_out;

    const int smemNufft = (A_FLOATS + 2 * B_FLOATS) * (int)sizeof(float)
                        + 96 * 4 * (int)sizeof(float2);    // ~185KB
    cudaFuncSetAttribute(nufft_mma_kernel,
                         cudaFuncAttributeMaxDynamicSharedMemorySize, smemNufft);

    transpose_kernel<<<dim3(16, 16), 256>>>(singulars);
    exgen_kernel<<<NRO, 384>>>(ktraj);
    stageA_kernel<<<dim3(16, 48), 256>>>(smap);
    nufft_mma_kernel<<<dim3(NRO, 4), 512, smemNufft>>>(ur_list, sbin, out);
}